// round 7
// baseline (speedup 1.0000x reference)
#include <cuda_runtime.h>

#define BATCH   4
#define NPTS    16384
#define MFIX    256
#define NPALL   16640
#define NPOINT  2048
#define SQ      2304
#define NS      64
#define CIN     128
#define KH      136
#define MROWS   (BATCH*SQ*NS)
#define SB      512

#define OUT_FEAT_OFF 27648
#define OUT_INDS_OFF 2386944

__device__ float g_featsT[(size_t)BATCH*NPALL*CIN];
__device__ float g_allx[BATCH*NPALL];
__device__ float g_ally[BATCH*NPALL];
__device__ float g_allz[BATCH*NPALL];
__device__ float g_newxyz[BATCH*SQ*3];
__device__ int   g_inds[BATCH*NPOINT];
__device__ int   g_ballidx[MROWS];
__device__ float g_h [(size_t)MROWS*KH];
__device__ float g_o1[(size_t)MROWS*128];
__device__ float g_o2[(size_t)MROWS*128];
__device__ float g_o3[(size_t)MROWS*256];
__device__ float g_w1[KH*128];
__device__ float g_w2[128*128];
__device__ float g_w3[128*256];
__device__ float g_part[SB*2*256];
__device__ float g_scale[3*256];
__device__ float g_bias [3*256];

__global__ void k_prep_w(const float* __restrict__ W1, const float* __restrict__ W2,
                         const float* __restrict__ W3) {
    int i = blockIdx.x*256 + threadIdx.x;
    if (i < KH*128) {
        int k = i >> 7, o = i & 127;
        float v = 0.f;
        if (k < 128)      v = W1[o*131 + 3 + k];
        else if (k < 131) v = W1[o*131 + (k-128)];
        g_w1[i] = v;
    } else if (i < KH*128 + 128*128) {
        int j = i - KH*128; int k = j >> 7, o = j & 127;
        g_w2[j] = W2[o*128 + k];
    } else if (i < KH*128 + 128*128 + 128*256) {
        int j = i - KH*128 - 128*128; int k = j >> 8, o = j & 255;
        g_w3[j] = W3[o*128 + k];
    }
}

__global__ void k_transpose(const float* __restrict__ F) {
    __shared__ float t[32][33];
    int b = blockIdx.z, p0 = blockIdx.x*32, c0 = blockIdx.y*32;
    for (int j = threadIdx.y; j < 32; j += 8)
        t[j][threadIdx.x] = F[((size_t)b*CIN + c0 + j)*NPALL + p0 + threadIdx.x];
    __syncthreads();
    for (int j = threadIdx.y; j < 32; j += 8)
        g_featsT[((size_t)b*NPALL + p0 + j)*CIN + c0 + threadIdx.x] = t[threadIdx.x][j];
}

__global__ void k_build_all(const float* __restrict__ fixed_xyz, const float* __restrict__ xyz) {
    int i = blockIdx.x*256 + threadIdx.x;
    if (i >= BATCH*NPALL) return;
    int b = i / NPALL, p = i - b*NPALL;
    const float* src = (p < MFIX) ? (fixed_xyz + ((size_t)b*MFIX + p)*3)
                                  : (xyz       + ((size_t)b*NPTS + (p-MFIX))*3);
    g_allx[i] = src[0]; g_ally[i] = src[1]; g_allz[i] = src[2];
}

__global__ void k_copy_fixed(const float* __restrict__ fixed_xyz) {
    int i = blockIdx.x*256 + threadIdx.x;
    if (i >= BATCH*MFIX*3) return;
    int b = i / (MFIX*3), r = i - b*(MFIX*3);
    g_newxyz[b*(SQ*3) + r] = fixed_xyz[i];
}

// exact reference arithmetic: ((dx*dx + dy*dy) + dz*dz), no fma
__device__ __forceinline__ float d2ref(float dx, float dy, float dz) {
    return __fadd_rn(__fadd_rn(__fmul_rn(dx,dx), __fmul_rn(dy,dy)), __fmul_rn(dz,dz));
}

__global__ void k_fps(const float* __restrict__ xyz) {
    extern __shared__ float sm[];
    float* xs = sm; float* ys = sm + NPTS; float* zs = sm + 2*NPTS;
    __shared__ unsigned long long skey[32];
    __shared__ float s_l[3];
    int b = blockIdx.x, tid = threadIdx.x;
    const float* base = xyz + (size_t)b*NPTS*3;
    for (int t = tid; t < NPTS*3; t += 1024) {
        float v = base[t]; int p = t/3, c = t - p*3;
        if (c == 0) xs[p] = v; else if (c == 1) ys[p] = v; else zs[p] = v;
    }
    float dist[16];
    #pragma unroll
    for (int j = 0; j < 16; j++) dist[j] = 1e10f;
    __syncthreads();
    if (tid == 0) {
        s_l[0] = xs[0]; s_l[1] = ys[0]; s_l[2] = zs[0];
        g_inds[b*NPOINT] = 0;
        int d = (b*SQ + MFIX)*3;
        g_newxyz[d] = xs[0]; g_newxyz[d+1] = ys[0]; g_newxyz[d+2] = zs[0];
    }
    __syncthreads();
    int wid = tid >> 5, lane = tid & 31;
    for (int it = 1; it < NPOINT; ++it) {
        float lx = s_l[0], ly = s_l[1], lz = s_l[2];
        float bd = -1.f; int bi = 0;
        #pragma unroll
        for (int j = 0; j < 16; j++) {
            int p = tid + j*1024;
            float d = d2ref(xs[p]-lx, ys[p]-ly, zs[p]-lz);
            float nd = fminf(dist[j], d);
            dist[j] = nd;
            if (nd > bd) { bd = nd; bi = p; }
        }
        unsigned long long key = ((unsigned long long)__float_as_uint(bd) << 32)
                               | (unsigned)(0xFFFFFFFFu - (unsigned)bi);
        #pragma unroll
        for (int o = 16; o; o >>= 1) {
            unsigned long long k2 = __shfl_down_sync(0xffffffffu, key, o);
            if (k2 > key) key = k2;
        }
        if (!lane) skey[wid] = key;
        __syncthreads();
        if (wid == 0) {
            key = skey[lane];
            #pragma unroll
            for (int o = 16; o; o >>= 1) {
                unsigned long long k2 = __shfl_down_sync(0xffffffffu, key, o);
                if (k2 > key) key = k2;
            }
            if (!lane) {
                int sel = (int)(0xFFFFFFFFu - (unsigned)(key & 0xffffffffull));
                g_inds[b*NPOINT + it] = sel;
                float px = xs[sel], py = ys[sel], pz = zs[sel];
                s_l[0] = px; s_l[1] = py; s_l[2] = pz;
                int d = (b*SQ + MFIX + it)*3;
                g_newxyz[d] = px; g_newxyz[d+1] = py; g_newxyz[d+2] = pz;
            }
        }
        __syncthreads();
    }
}

__global__ void k_ball() {
    extern __shared__ float sm[];
    float* xs = sm; float* ys = sm + NPALL; float* zs = sm + 2*NPALL;
    int* lists = (int*)(sm + 3*NPALL);
    int b = blockIdx.y, tid = threadIdx.x;
    for (int t = tid; t < NPALL; t += 512) {
        int gi = b*NPALL + t;
        xs[t] = g_allx[gi]; ys[t] = g_ally[gi]; zs[t] = g_allz[gi];
    }
    __syncthreads();
    int w = tid >> 5, lane = tid & 31;
    int* list = lists + w*NS;
    unsigned lmask = (1u << lane) - 1u;
    for (int qi = w; qi < 48; qi += 16) {
        int s = blockIdx.x*48 + qi;
        const float* q = g_newxyz + (size_t)(b*SQ + s)*3;
        float qx = q[0], qy = q[1], qz = q[2];
        int cnt = 0;
        for (int base = 0; base < NPALL; base += 32) {
            int p = base + lane;
            float d2 = d2ref(xs[p]-qx, ys[p]-qy, zs[p]-qz);
            bool hit = d2 < 0.04f;
            unsigned mask = __ballot_sync(0xffffffffu, hit);
            int pos = cnt + __popc(mask & lmask);
            if (hit && pos < NS) list[pos] = p;
            cnt += __popc(mask);
            if (cnt >= NS) break;
        }
        __syncwarp();
        int total = cnt < NS ? cnt : NS;
        int first = (total > 0) ? list[0] : 0;
        int ob = (b*SQ + s)*NS;
        for (int j = lane; j < NS; j += 32)
            g_ballidx[ob + j] = (j < total) ? list[j] : first;
        __syncwarp();
    }
}

__global__ void k_gather() {
    int r = blockIdx.x*8 + (threadIdx.x >> 5);
    int lane = threadIdx.x & 31;
    if (r >= MROWS) return;
    int idx = g_ballidx[r];
    int b = r / (SQ*NS);
    int s = (r / NS) % SQ;
    size_t hb = (size_t)r * KH;
    const float4* src = (const float4*)(g_featsT + ((size_t)b*NPALL + idx)*CIN);
    ((float4*)(g_h + hb))[lane] = src[lane];
    if (lane == 0) {
        const float* q = g_newxyz + (size_t)(b*SQ + s)*3;
        int ai = b*NPALL + idx;
        float gx = __fdiv_rn(__fsub_rn(g_allx[ai], q[0]), 0.2f);
        float gy = __fdiv_rn(__fsub_rn(g_ally[ai], q[1]), 0.2f);
        float gz = __fdiv_rn(__fsub_rn(g_allz[ai], q[2]), 0.2f);
        *(float4*)(g_h + hb + 128) = make_float4(gx, gy, gz, 0.f);
        *(float4*)(g_h + hb + 132) = make_float4(0.f, 0.f, 0.f, 0.f);
    }
}

template<int TRANSFORM>
__global__ __launch_bounds__(256, 2)
void k_gemm(const float* __restrict__ A, int lda,
            const float* __restrict__ Bw, int ldb,
            float* __restrict__ C, int ldc, int K,
            const float* __restrict__ sc, const float* __restrict__ bi) {
    __shared__ float As[8][132];
    __shared__ float Bs[8][128];
    __shared__ float s_sc[KH], s_bi[KH];
    int tid = threadIdx.x;
    int m0 = blockIdx.x*128, n0 = blockIdx.y*128;
    int arow = tid >> 1, acol = (tid & 1)*4;
    int brow = tid >> 5, bcol = (tid & 31)*4;
    const float* Ap = A + (size_t)(m0 + arow)*lda + acol;
    const float* Bp = Bw + (size_t)brow*ldb + n0 + bcol;
    if (TRANSFORM) {
        for (int i = tid; i < K; i += 256) { s_sc[i] = sc[i]; s_bi[i] = bi[i]; }
    }
    __syncthreads();
    float acc[8][8];
    #pragma unroll
    for (int i = 0; i < 8; i++)
        #pragma unroll
        for (int j = 0; j < 8; j++) acc[i][j] = 0.f;
    int rb = (tid >> 4)*8, cb = (tid & 15)*8;
    for (int k0 = 0; k0 < K; k0 += 8) {
        float4 a  = *(const float4*)(Ap + k0);
        float4 bv = *(const float4*)(Bp + (size_t)k0*ldb);
        if (TRANSFORM) {
            a.x = fmaxf(0.f, fmaf(a.x, s_sc[k0+acol+0], s_bi[k0+acol+0]));
            a.y = fmaxf(0.f, fmaf(a.y, s_sc[k0+acol+1], s_bi[k0+acol+1]));
            a.z = fmaxf(0.f, fmaf(a.z, s_sc[k0+acol+2], s_bi[k0+acol+2]));
            a.w = fmaxf(0.f, fmaf(a.w, s_sc[k0+acol+3], s_bi[k0+acol+3]));
        }
        As[acol+0][arow] = a.x; As[acol+1][arow] = a.y;
        As[acol+2][arow] = a.z; As[acol+3][arow] = a.w;
        *(float4*)&Bs[brow][bcol] = bv;
        __syncthreads();
        #pragma unroll
        for (int kk = 0; kk < 8; kk++) {
            float ar[8], br[8];
            *(float4*)(ar)   = *(const float4*)&As[kk][rb];
            *(float4*)(ar+4) = *(const float4*)&As[kk][rb+4];
            *(float4*)(br)   = *(const float4*)&Bs[kk][cb];
            *(float4*)(br+4) = *(const float4*)&Bs[kk][cb+4];
            #pragma unroll
            for (int i = 0; i < 8; i++)
                #pragma unroll
                for (int j = 0; j < 8; j++)
                    acc[i][j] = fmaf(ar[i], br[j], acc[i][j]);
        }
        __syncthreads();
    }
    float* Cp = C + (size_t)(m0 + rb)*ldc + n0 + cb;
    #pragma unroll
    for (int i = 0; i < 8; i++) {
        *(float4*)(Cp + (size_t)i*ldc)     = make_float4(acc[i][0], acc[i][1], acc[i][2], acc[i][3]);
        *(float4*)(Cp + (size_t)i*ldc + 4) = make_float4(acc[i][4], acc[i][5], acc[i][6], acc[i][7]);
    }
}

__global__ void k_stats(const float* __restrict__ X, int Nch) {
    int tid = threadIdx.x;
    float s = 0.f, s2 = 0.f;
    if (Nch == 128) {
        int col = tid & 127, rg = tid >> 7;
        for (int r = blockIdx.x*2 + rg; r < MROWS; r += SB*2) {
            float v = X[(size_t)r*128 + col]; s += v; s2 = fmaf(v, v, s2);
        }
        __shared__ float sa[256], sb[256];
        sa[tid] = s; sb[tid] = s2; __syncthreads();
        if (tid < 128) {
            g_part[(blockIdx.x*2    )*256 + tid] = sa[tid] + sa[tid+128];
            g_part[(blockIdx.x*2 + 1)*256 + tid] = sb[tid] + sb[tid+128];
        }
    } else {
        int col = tid;
        for (int r = blockIdx.x; r < MROWS; r += SB) {
            float v = X[(size_t)r*256 + col]; s += v; s2 = fmaf(v, v, s2);
        }
        g_part[(blockIdx.x*2    )*256 + tid] = s;
        g_part[(blockIdx.x*2 + 1)*256 + tid] = s2;
    }
}

__global__ void k_finalize(int Nch, const float* __restrict__ g, const float* __restrict__ b,
                           float* __restrict__ scale, float* __restrict__ bias) {
    int c = threadIdx.x;
    if (c >= Nch) return;
    float s = 0.f, s2 = 0.f;
    for (int i = 0; i < SB; i++) {
        s  += g_part[(i*2    )*256 + c];
        s2 += g_part[(i*2 + 1)*256 + c];
    }
    float inv = 1.f / (float)MROWS;
    float mean = s * inv;
    float var = fmaxf(0.f, s2 * inv - mean*mean);
    float sc = g[c] * rsqrtf(var + 1e-5f);
    scale[c] = sc;
    bias[c]  = b[c] - mean * sc;
}

__global__ void k_maxpool(const float* __restrict__ sc, const float* __restrict__ bi,
                          float* __restrict__ out) {
    int bs = blockIdx.x;            // 0..BATCH*SQ-1
    int o  = threadIdx.x;           // 0..255
    int b = bs / SQ, s = bs - b*SQ;
    float scl = sc[o], bia = bi[o];
    const float* row = g_o3 + (size_t)bs*NS*256 + o;
    float m = -1e30f;
    #pragma unroll 4
    for (int k = 0; k < NS; k++) {
        float v = fmaf(row[(size_t)k*256], scl, bia);
        m = fmaxf(m, v);
    }
    m = fmaxf(m, 0.f);
    out[OUT_FEAT_OFF + ((size_t)(b*256 + o))*SQ + s] = m;
}

__global__ void k_writeout(float* __restrict__ out) {
    int i = blockIdx.x*256 + threadIdx.x;
    if (i < BATCH*SQ*3) out[i] = g_newxyz[i];
    if (i < BATCH*NPOINT) out[OUT_INDS_OFF + i] = (float)g_inds[i];
}

extern "C" void kernel_launch(void* const* d_in, const int* in_sizes, int n_in,
                              void* d_out, int out_size) {
    const float* fixed_xyz = (const float*)d_in[0];
    const float* xyz       = (const float*)d_in[1];
    const float* features  = (const float*)d_in[2];
    const float* W1 = (const float*)d_in[3];
    const float* g1 = (const float*)d_in[4];
    const float* b1 = (const float*)d_in[5];
    const float* W2 = (const float*)d_in[6];
    const float* g2 = (const float*)d_in[7];
    const float* b2 = (const float*)d_in[8];
    const float* W3 = (const float*)d_in[9];
    const float* g3 = (const float*)d_in[10];
    const float* b3 = (const float*)d_in[11];
    float* out = (float*)d_out;

    static bool attr_done = false;
    if (!attr_done) {
        cudaFuncSetAttribute(k_fps,  cudaFuncAttributeMaxDynamicSharedMemorySize, 3*NPTS*4);
        cudaFuncSetAttribute(k_ball, cudaFuncAttributeMaxDynamicSharedMemorySize, 3*NPALL*4 + 16*NS*4);
        attr_done = true;
    }

    float* sc0 = nullptr; float* bi0 = nullptr;
    cudaGetSymbolAddress((void**)&sc0, g_scale);
    cudaGetSymbolAddress((void**)&bi0, g_bias);

    float* gw1; float* gw2; float* gw3;
    cudaGetSymbolAddress((void**)&gw1, g_w1);
    cudaGetSymbolAddress((void**)&gw2, g_w2);
    cudaGetSymbolAddress((void**)&gw3, g_w3);
    float* gh; float* go1; float* go2; float* go3;
    cudaGetSymbolAddress((void**)&gh,  g_h);
    cudaGetSymbolAddress((void**)&go1, g_o1);
    cudaGetSymbolAddress((void**)&go2, g_o2);
    cudaGetSymbolAddress((void**)&go3, g_o3);

    k_prep_w<<<(KH*128 + 128*128 + 128*256 + 255)/256, 256>>>(W1, W2, W3);
    k_transpose<<<dim3(NPALL/32, CIN/32, BATCH), dim3(32,8)>>>(features);
    k_build_all<<<(BATCH*NPALL + 255)/256, 256>>>(fixed_xyz, xyz);
    k_copy_fixed<<<(BATCH*MFIX*3 + 255)/256, 256>>>(fixed_xyz);
    k_fps<<<BATCH, 1024, 3*NPTS*4>>>(xyz);
    k_ball<<<dim3(SQ/48, BATCH), 512, 3*NPALL*4 + 16*NS*4>>>();
    k_gather<<<MROWS/8, 256>>>();

    // layer 1: o1 = h @ W1^T   (K=136, no input transform)
    k_gemm<0><<<dim3(MROWS/128, 1), 256>>>(gh, KH, gw1, 128, go1, 128, KH, nullptr, nullptr);
    k_stats<<<SB, 256>>>(go1, 128);
    k_finalize<<<1, 256>>>(128, g1, b1, sc0 + 0*256, bi0 + 0*256);

    // layer 2: o2 = bn_relu(o1) @ W2^T
    k_gemm<1><<<dim3(MROWS/128, 1), 256>>>(go1, 128, gw2, 128, go2, 128, 128, sc0 + 0*256, bi0 + 0*256);
    k_stats<<<SB, 256>>>(go2, 128);
    k_finalize<<<1, 256>>>(128, g2, b2, sc0 + 1*256, bi0 + 1*256);

    // layer 3: o3 = bn_relu(o2) @ W3^T  (N=256)
    k_gemm<1><<<dim3(MROWS/128, 2), 256>>>(go2, 128, gw3, 256, go3, 256, 128, sc0 + 1*256, bi0 + 1*256);
    k_stats<<<SB, 256>>>(go3, 256);
    k_finalize<<<1, 256>>>(256, g3, b3, sc0 + 2*256, bi0 + 2*256);

    // bn_relu(o3) folded into max-pool; outputs
    k_maxpool<<<BATCH*SQ, 256>>>(sc0 + 2*256, bi0 + 2*256, out);
    k_writeout<<<(BATCH*SQ*3 + 255)/256, 256>>>(out);
}

// round 8
// speedup vs baseline: 1.0835x; 1.0835x over previous
#include <cuda_runtime.h>

#define BATCH   4
#define NPTS    16384
#define MFIX    256
#define NPALL   16640
#define NPOINT  2048
#define SQ      2304
#define NS      64
#define CIN     128
#define KH      144
#define MROWS   (BATCH*SQ*NS)
#define NMB     (MROWS/128)

#define OUT_FEAT_OFF 27648
#define OUT_INDS_OFF 2386944

__device__ float g_featsT[(size_t)BATCH*NPALL*CIN];
__device__ float g_allx[BATCH*NPALL];
__device__ float g_ally[BATCH*NPALL];
__device__ float g_allz[BATCH*NPALL];
__device__ float g_newxyz[BATCH*SQ*3];
__device__ int   g_inds[BATCH*NPOINT];
__device__ int   g_ballidx[MROWS];
__device__ float g_h [(size_t)MROWS*KH];
__device__ float g_o1[(size_t)MROWS*128];
__device__ float g_o2[(size_t)MROWS*128];
__device__ float g_o3[(size_t)MROWS*256];
__device__ unsigned g_w1h[KH*128],  g_w1l[KH*128];
__device__ unsigned g_w2h[128*128], g_w2l[128*128];
__device__ unsigned g_w3h[128*256], g_w3l[128*256];
__device__ float g_part[(size_t)NMB*512];
__device__ float g_scale[3*256];
__device__ float g_bias [3*256];

__device__ __forceinline__ void split32(float x, unsigned &h, unsigned &l) {
    asm("cvt.rna.tf32.f32 %0, %1;" : "=r"(h) : "f"(x));
    float r = __fsub_rn(x, __uint_as_float(h));
    asm("cvt.rna.tf32.f32 %0, %1;" : "=r"(l) : "f"(r));
}

__device__ __forceinline__ void mma8(float* c, unsigned a0, unsigned a1, unsigned a2, unsigned a3,
                                     unsigned b0, unsigned b1) {
    asm volatile("mma.sync.aligned.m16n8k8.row.col.f32.tf32.tf32.f32 "
        "{%0,%1,%2,%3}, {%4,%5,%6,%7}, {%8,%9}, {%0,%1,%2,%3};"
        : "+f"(c[0]), "+f"(c[1]), "+f"(c[2]), "+f"(c[3])
        : "r"(a0), "r"(a1), "r"(a2), "r"(a3), "r"(b0), "r"(b1));
}

__global__ void k_prep_w(const float* __restrict__ W1, const float* __restrict__ W2,
                         const float* __restrict__ W3) {
    int i = blockIdx.x*256 + threadIdx.x;
    const int N1 = KH*128, N2 = 128*128, N3 = 128*256;
    if (i < N1) {
        int k = i >> 7, o = i & 127;
        float v = 0.f;
        if (k < 128)      v = W1[o*131 + 3 + k];
        else if (k < 131) v = W1[o*131 + (k-128)];
        unsigned h,l; split32(v,h,l);
        g_w1h[k*128+o]=h; g_w1l[k*128+o]=l;
    } else if (i < N1+N2) {
        int j=i-N1; int k=j>>7, o=j&127;
        unsigned h,l; split32(W2[o*128+k],h,l);
        g_w2h[k*128+o]=h; g_w2l[k*128+o]=l;
    } else if (i < N1+N2+N3) {
        int j=i-N1-N2; int k=j>>8, o=j&255;
        unsigned h,l; split32(W3[o*128+k],h,l);
        g_w3h[k*256+o]=h; g_w3l[k*256+o]=l;
    }
}

__global__ void k_transpose(const float* __restrict__ F) {
    __shared__ float t[32][33];
    int b = blockIdx.z, p0 = blockIdx.x*32, c0 = blockIdx.y*32;
    for (int j = threadIdx.y; j < 32; j += 8)
        t[j][threadIdx.x] = F[((size_t)b*CIN + c0 + j)*NPALL + p0 + threadIdx.x];
    __syncthreads();
    for (int j = threadIdx.y; j < 32; j += 8)
        g_featsT[((size_t)b*NPALL + p0 + j)*CIN + c0 + threadIdx.x] = t[threadIdx.x][j];
}

__global__ void k_build_all(const float* __restrict__ fixed_xyz, const float* __restrict__ xyz) {
    int i = blockIdx.x*256 + threadIdx.x;
    if (i >= BATCH*NPALL) return;
    int b = i / NPALL, p = i - b*NPALL;
    const float* src = (p < MFIX) ? (fixed_xyz + ((size_t)b*MFIX + p)*3)
                                  : (xyz       + ((size_t)b*NPTS + (p-MFIX))*3);
    g_allx[i] = src[0]; g_ally[i] = src[1]; g_allz[i] = src[2];
}

__global__ void k_copy_fixed(const float* __restrict__ fixed_xyz) {
    int i = blockIdx.x*256 + threadIdx.x;
    if (i >= BATCH*MFIX*3) return;
    int b = i / (MFIX*3), r = i - b*(MFIX*3);
    g_newxyz[b*(SQ*3) + r] = fixed_xyz[i];
}

__device__ __forceinline__ float d2ref(float dx, float dy, float dz) {
    return __fadd_rn(__fadd_rn(__fmul_rn(dx,dx), __fmul_rn(dy,dy)), __fmul_rn(dz,dz));
}

__global__ void k_fps(const float* __restrict__ xyz) {
    extern __shared__ float sm[];
    float* xs = sm; float* ys = sm + NPTS; float* zs = sm + 2*NPTS;
    __shared__ unsigned long long skey[32];
    __shared__ float s_l[3];
    int b = blockIdx.x, tid = threadIdx.x;
    const float* base = xyz + (size_t)b*NPTS*3;
    for (int t = tid; t < NPTS*3; t += 1024) {
        float v = base[t]; int p = t/3, c = t - p*3;
        if (c == 0) xs[p] = v; else if (c == 1) ys[p] = v; else zs[p] = v;
    }
    float dist[16];
    #pragma unroll
    for (int j = 0; j < 16; j++) dist[j] = 1e10f;
    __syncthreads();
    if (tid == 0) {
        s_l[0] = xs[0]; s_l[1] = ys[0]; s_l[2] = zs[0];
        g_inds[b*NPOINT] = 0;
        int d = (b*SQ + MFIX)*3;
        g_newxyz[d] = xs[0]; g_newxyz[d+1] = ys[0]; g_newxyz[d+2] = zs[0];
    }
    __syncthreads();
    int wid = tid >> 5, lane = tid & 31;
    for (int it = 1; it < NPOINT; ++it) {
        float lx = s_l[0], ly = s_l[1], lz = s_l[2];
        float bd = -1.f; int bi = 0;
        #pragma unroll
        for (int j = 0; j < 16; j++) {
            int p = tid + j*1024;
            float d = d2ref(xs[p]-lx, ys[p]-ly, zs[p]-lz);
            float nd = fminf(dist[j], d);
            dist[j] = nd;
            if (nd > bd) { bd = nd; bi = p; }
        }
        unsigned long long key = ((unsigned long long)__float_as_uint(bd) << 32)
                               | (unsigned)(0xFFFFFFFFu - (unsigned)bi);
        #pragma unroll
        for (int o = 16; o; o >>= 1) {
            unsigned long long k2 = __shfl_down_sync(0xffffffffu, key, o);
            if (k2 > key) key = k2;
        }
        if (!lane) skey[wid] = key;
        __syncthreads();
        if (wid == 0) {
            key = skey[lane];
            #pragma unroll
            for (int o = 16; o; o >>= 1) {
                unsigned long long k2 = __shfl_down_sync(0xffffffffu, key, o);
                if (k2 > key) key = k2;
            }
            if (!lane) {
                int sel = (int)(0xFFFFFFFFu - (unsigned)(key & 0xffffffffull));
                g_inds[b*NPOINT + it] = sel;
                float px = xs[sel], py = ys[sel], pz = zs[sel];
                s_l[0] = px; s_l[1] = py; s_l[2] = pz;
                int d = (b*SQ + MFIX + it)*3;
                g_newxyz[d] = px; g_newxyz[d+1] = py; g_newxyz[d+2] = pz;
            }
        }
        __syncthreads();
    }
}

__global__ void k_ball() {
    extern __shared__ float sm[];
    float* xs = sm; float* ys = sm + NPALL; float* zs = sm + 2*NPALL;
    int* lists = (int*)(sm + 3*NPALL);
    int b = blockIdx.y, tid = threadIdx.x;
    for (int t = tid; t < NPALL; t += 512) {
        int gi = b*NPALL + t;
        xs[t] = g_allx[gi]; ys[t] = g_ally[gi]; zs[t] = g_allz[gi];
    }
    __syncthreads();
    int w = tid >> 5, lane = tid & 31;
    int* list = lists + w*NS;
    unsigned lmask = (1u << lane) - 1u;
    for (int qi = w; qi < 48; qi += 16) {
        int s = blockIdx.x*48 + qi;
        const float* q = g_newxyz + (size_t)(b*SQ + s)*3;
        float qx = q[0], qy = q[1], qz = q[2];
        int cnt = 0;
        for (int base = 0; base < NPALL; base += 32) {
            int p = base + lane;
            float d2 = d2ref(xs[p]-qx, ys[p]-qy, zs[p]-qz);
            bool hit = d2 < 0.04f;
            unsigned mask = __ballot_sync(0xffffffffu, hit);
            int pos = cnt + __popc(mask & lmask);
            if (hit && pos < NS) list[pos] = p;
            cnt += __popc(mask);
            if (cnt >= NS) break;
        }
        __syncwarp();
        int total = cnt < NS ? cnt : NS;
        int first = (total > 0) ? list[0] : 0;
        int ob = (b*SQ + s)*NS;
        for (int j = lane; j < NS; j += 32)
            g_ballidx[ob + j] = (j < total) ? list[j] : first;
        __syncwarp();
    }
}

__global__ void k_gather() {
    int r = blockIdx.x*8 + (threadIdx.x >> 5);
    int lane = threadIdx.x & 31;
    if (r >= MROWS) return;
    int idx = g_ballidx[r];
    int b = r / (SQ*NS);
    int s = (r / NS) % SQ;
    size_t hb = (size_t)r * KH;
    const float4* src = (const float4*)(g_featsT + ((size_t)b*NPALL + idx)*CIN);
    ((float4*)(g_h + hb))[lane] = src[lane];
    if (lane < 4) {
        float4 pad = make_float4(0.f, 0.f, 0.f, 0.f);
        if (lane == 0) {
            const float* q = g_newxyz + (size_t)(b*SQ + s)*3;
            int ai = b*NPALL + idx;
            pad.x = __fdiv_rn(__fsub_rn(g_allx[ai], q[0]), 0.2f);
            pad.y = __fdiv_rn(__fsub_rn(g_ally[ai], q[1]), 0.2f);
            pad.z = __fdiv_rn(__fsub_rn(g_allz[ai], q[2]), 0.2f);
        }
        *(float4*)(g_h + hb + 128 + lane*4) = pad;
    }
}

// ---------------- 3xTF32 GEMM: 128x128 CTA tile, BK=16, fused bn_relu(A) + stats ----------------
#define SMA (16*136)

template<int TRANSFORM>
__global__ __launch_bounds__(256, 1)
void k_gemm_tf32(const float* __restrict__ A, int lda,
                 const unsigned* __restrict__ Bh, const unsigned* __restrict__ Bl, int ldb,
                 float* __restrict__ C, int ldc, int K,
                 const float* __restrict__ sc, const float* __restrict__ bi) {
    extern __shared__ unsigned smu[];
    unsigned* Ah  = smu;
    unsigned* Al  = Ah  + 2*SMA;
    unsigned* Bhs = Al  + 2*SMA;
    unsigned* Bls = Bhs + 2*SMA;
    float* s_sc = (float*)(Bls + 2*SMA);
    float* s_bi = s_sc + KH;
    float* red  = s_bi + KH;   // 512 floats

    const int tid = threadIdx.x;
    const int m0 = blockIdx.x*128, n0 = blockIdx.y*128;
    const int lane = tid & 31, wid = tid >> 5;
    const int gid = lane >> 2, tig = lane & 3;
    const int wm = wid & 1, wn = wid >> 1;

    if (TRANSFORM) {
        for (int i = tid; i < K; i += 256) { s_sc[i] = sc[i]; s_bi[i] = bi[i]; }
        __syncthreads();
    }

    const int lrow = tid >> 1;
    const int lk   = (tid & 1) * 8;
    const float* Agl = A + (size_t)(m0 + lrow)*lda + lk;
    const int bk0 = tid >> 5;
    const int bnq = (tid & 31) * 4;

    float acc[4][4][4];
    #pragma unroll
    for (int i = 0; i < 4; i++)
        #pragma unroll
        for (int j = 0; j < 4; j++)
            #pragma unroll
            for (int r = 0; r < 4; r++) acc[i][j][r] = 0.f;

    const int S = K >> 4;
    float a8[8];
    uint4 vh0, vh1, vl0, vl1;

    {   // prefetch stage 0
        float4 p0 = *(const float4*)(Agl);
        float4 p1 = *(const float4*)(Agl + 4);
        a8[0]=p0.x; a8[1]=p0.y; a8[2]=p0.z; a8[3]=p0.w;
        a8[4]=p1.x; a8[5]=p1.y; a8[6]=p1.z; a8[7]=p1.w;
        vh0 = *(const uint4*)(Bh + (size_t)bk0*ldb + n0 + bnq);
        vh1 = *(const uint4*)(Bh + (size_t)(bk0+8)*ldb + n0 + bnq);
        vl0 = *(const uint4*)(Bl + (size_t)bk0*ldb + n0 + bnq);
        vl1 = *(const uint4*)(Bl + (size_t)(bk0+8)*ldb + n0 + bnq);
    }

    for (int s = 0; s < S; s++) {
        // store prefetched stage s -> buffer s&1 (split to hi/lo, transform A)
        {
            unsigned* Ad  = Ah  + (s&1)*SMA;
            unsigned* Ald = Al  + (s&1)*SMA;
            #pragma unroll
            for (int j = 0; j < 8; j++) {
                float x = a8[j];
                if (TRANSFORM) {
                    int k = (s<<4) + lk + j;
                    x = fmaxf(0.f, fmaf(x, s_sc[k], s_bi[k]));
                }
                unsigned h, l; split32(x, h, l);
                Ad [(lk+j)*136 + lrow] = h;
                Ald[(lk+j)*136 + lrow] = l;
            }
            unsigned* Bd  = Bhs + (s&1)*SMA;
            unsigned* Bld = Bls + (s&1)*SMA;
            *(uint4*)(Bd  + bk0*136     + bnq) = vh0;
            *(uint4*)(Bd  + (bk0+8)*136 + bnq) = vh1;
            *(uint4*)(Bld + bk0*136     + bnq) = vl0;
            *(uint4*)(Bld + (bk0+8)*136 + bnq) = vl1;
        }
        __syncthreads();
        // prefetch stage s+1
        if (s+1 < S) {
            int K0 = (s+1) << 4;
            float4 p0 = *(const float4*)(Agl + K0);
            float4 p1 = *(const float4*)(Agl + K0 + 4);
            a8[0]=p0.x; a8[1]=p0.y; a8[2]=p0.z; a8[3]=p0.w;
            a8[4]=p1.x; a8[5]=p1.y; a8[6]=p1.z; a8[7]=p1.w;
            vh0 = *(const uint4*)(Bh + (size_t)(K0+bk0)*ldb + n0 + bnq);
            vh1 = *(const uint4*)(Bh + (size_t)(K0+bk0+8)*ldb + n0 + bnq);
            vl0 = *(const uint4*)(Bl + (size_t)(K0+bk0)*ldb + n0 + bnq);
            vl1 = *(const uint4*)(Bl + (size_t)(K0+bk0+8)*ldb + n0 + bnq);
        }
        // compute stage s
        const unsigned* Ahc = Ah  + (s&1)*SMA;
        const unsigned* Alc = Al  + (s&1)*SMA;
        const unsigned* Bhc = Bhs + (s&1)*SMA;
        const unsigned* Blc = Bls + (s&1)*SMA;
        #pragma unroll
        for (int kk = 0; kk < 16; kk += 8) {
            unsigned bh[4][2], bl[4][2];
            #pragma unroll
            for (int nt = 0; nt < 4; nt++) {
                int nb = wn*32 + nt*8 + gid;
                bh[nt][0] = Bhc[(kk+tig  )*136 + nb];
                bh[nt][1] = Bhc[(kk+tig+4)*136 + nb];
                bl[nt][0] = Blc[(kk+tig  )*136 + nb];
                bl[nt][1] = Blc[(kk+tig+4)*136 + nb];
            }
            #pragma unroll
            for (int mt = 0; mt < 4; mt++) {
                int mb = wm*64 + mt*16 + gid;
                unsigned ah0 = Ahc[(kk+tig  )*136 + mb];
                unsigned ah1 = Ahc[(kk+tig  )*136 + mb + 8];
                unsigned ah2 = Ahc[(kk+tig+4)*136 + mb];
                unsigned ah3 = Ahc[(kk+tig+4)*136 + mb + 8];
                unsigned al0 = Alc[(kk+tig  )*136 + mb];
                unsigned al1 = Alc[(kk+tig  )*136 + mb + 8];
                unsigned al2 = Alc[(kk+tig+4)*136 + mb];
                unsigned al3 = Alc[(kk+tig+4)*136 + mb + 8];
                #pragma unroll
                for (int nt = 0; nt < 4; nt++) {
                    mma8(acc[mt][nt], al0,al1,al2,al3, bh[nt][0], bh[nt][1]);
                    mma8(acc[mt][nt], ah0,ah1,ah2,ah3, bl[nt][0], bl[nt][1]);
                    mma8(acc[mt][nt], ah0,ah1,ah2,ah3, bh[nt][0], bh[nt][1]);
                }
            }
        }
    }

    // epilogue: store C + per-block channel partial sums (deterministic)
    float sAcc[8], sSq[8];
    #pragma unroll
    for (int j = 0; j < 8; j++) { sAcc[j] = 0.f; sSq[j] = 0.f; }
    #pragma unroll
    for (int mt = 0; mt < 4; mt++) {
        int row = m0 + wm*64 + mt*16 + gid;
        #pragma unroll
        for (int nt = 0; nt < 4; nt++) {
            int col = n0 + wn*32 + nt*8 + 2*tig;
            float c0 = acc[mt][nt][0], c1 = acc[mt][nt][1];
            float c2 = acc[mt][nt][2], c3 = acc[mt][nt][3];
            *(float2*)(C + (size_t)row*ldc + col)     = make_float2(c0, c1);
            *(float2*)(C + (size_t)(row+8)*ldc + col) = make_float2(c2, c3);
            sAcc[nt*2]   += c0 + c2;  sSq[nt*2]   += c0*c0 + c2*c2;
            sAcc[nt*2+1] += c1 + c3;  sSq[nt*2+1] += c1*c1 + c3*c3;
        }
    }
    #pragma unroll
    for (int off = 16; off >= 4; off >>= 1)
        #pragma unroll
        for (int j = 0; j < 8; j++) {
            sAcc[j] += __shfl_down_sync(0xffffffffu, sAcc[j], off);
            sSq[j]  += __shfl_down_sync(0xffffffffu, sSq[j],  off);
        }
    __syncthreads();
    if (lane < 4) {
        #pragma unroll
        for (int j = 0; j < 8; j++) {
            int colL = wn*32 + (j>>1)*8 + 2*lane + (j&1);
            red[wm*128 + colL]       = sAcc[j];
            red[256 + wm*128 + colL] = sSq[j];
        }
    }
    __syncthreads();
    if (tid < 128) {
        float s = red[tid]       + red[128 + tid];
        float q = red[256 + tid] + red[384 + tid];
        size_t pb = (size_t)blockIdx.x * 512;
        g_part[pb + n0 + tid]       = s;
        g_part[pb + 256 + n0 + tid] = q;
    }
}

__global__ void k_finalize2(const float* __restrict__ g, const float* __restrict__ b,
                            float* __restrict__ scale, float* __restrict__ bias) {
    int c = blockIdx.x, t = threadIdx.x;
    float s = 0.f, q = 0.f;
    for (int mb = t; mb < NMB; mb += 256) {
        s += g_part[(size_t)mb*512 + c];
        q += g_part[(size_t)mb*512 + 256 + c];
    }
    __shared__ float rs[256], rq[256];
    rs[t] = s; rq[t] = q; __syncthreads();
    for (int o = 128; o; o >>= 1) {
        if (t < o) { rs[t] += rs[t+o]; rq[t] += rq[t+o]; }
        __syncthreads();
    }
    if (!t) {
        float inv = 1.f / (float)MROWS;
        float mean = rs[0] * inv;
        float var = fmaxf(0.f, rq[0]*inv - mean*mean);
        float scv = g[c] * rsqrtf(var + 1e-5f);
        scale[c] = scv;
        bias[c]  = b[c] - mean * scv;
    }
}

__global__ void k_maxpool(const float* __restrict__ sc, const float* __restrict__ bi,
                          float* __restrict__ out) {
    int bs = blockIdx.x;
    int o  = threadIdx.x;
    int b = bs / SQ, s = bs - b*SQ;
    float scl = sc[o], bia = bi[o];
    const float* row = g_o3 + (size_t)bs*NS*256 + o;
    float m = -1e30f;
    #pragma unroll 4
    for (int k = 0; k < NS; k++) {
        float v = fmaf(row[(size_t)k*256], scl, bia);
        m = fmaxf(m, v);
    }
    m = fmaxf(m, 0.f);
    out[OUT_FEAT_OFF + ((size_t)(b*256 + o))*SQ + s] = m;
}

__global__ void k_writeout(float* __restrict__ out) {
    int i = blockIdx.x*256 + threadIdx.x;
    if (i < BATCH*SQ*3) out[i] = g_newxyz[i];
    if (i < BATCH*NPOINT) out[OUT_INDS_OFF + i] = (float)g_inds[i];
}

extern "C" void kernel_launch(void* const* d_in, const int* in_sizes, int n_in,
                              void* d_out, int out_size) {
    const float* fixed_xyz = (const float*)d_in[0];
    const float* xyz       = (const float*)d_in[1];
    const float* features  = (const float*)d_in[2];
    const float* W1 = (const float*)d_in[3];
    const float* g1 = (const float*)d_in[4];
    const float* b1 = (const float*)d_in[5];
    const float* W2 = (const float*)d_in[6];
    const float* g2 = (const float*)d_in[7];
    const float* b2 = (const float*)d_in[8];
    const float* W3 = (const float*)d_in[9];
    const float* g3 = (const float*)d_in[10];
    const float* b3 = (const float*)d_in[11];
    float* out = (float*)d_out;

    const int GEMM_SMEM = (8*SMA + 2*KH + 512) * 4;   // 72832 bytes

    static bool attr_done = false;
    if (!attr_done) {
        cudaFuncSetAttribute(k_fps,  cudaFuncAttributeMaxDynamicSharedMemorySize, 3*NPTS*4);
        cudaFuncSetAttribute(k_ball, cudaFuncAttributeMaxDynamicSharedMemorySize, 3*NPALL*4 + 16*NS*4);
        cudaFuncSetAttribute(k_gemm_tf32<0>, cudaFuncAttributeMaxDynamicSharedMemorySize, GEMM_SMEM);
        cudaFuncSetAttribute(k_gemm_tf32<1>, cudaFuncAttributeMaxDynamicSharedMemorySize, GEMM_SMEM);
        attr_done = true;
    }

    float *sc0, *bi0;
    cudaGetSymbolAddress((void**)&sc0, g_scale);
    cudaGetSymbolAddress((void**)&bi0, g_bias);
    unsigned *w1h, *w1l, *w2h, *w2l, *w3h, *w3l;
    cudaGetSymbolAddress((void**)&w1h, g_w1h);
    cudaGetSymbolAddress((void**)&w1l, g_w1l);
    cudaGetSymbolAddress((void**)&w2h, g_w2h);
    cudaGetSymbolAddress((void**)&w2l, g_w2l);
    cudaGetSymbolAddress((void**)&w3h, g_w3h);
    cudaGetSymbolAddress((void**)&w3l, g_w3l);
    float *gh, *go1, *go2, *go3;
    cudaGetSymbolAddress((void**)&gh,  g_h);
    cudaGetSymbolAddress((void**)&go1, g_o1);
    cudaGetSymbolAddress((void**)&go2, g_o2);
    cudaGetSymbolAddress((void**)&go3, g_o3);

    k_prep_w<<<(KH*128 + 128*128 + 128*256 + 255)/256, 256>>>(W1, W2, W3);
    k_transpose<<<dim3(NPALL/32, CIN/32, BATCH), dim3(32,8)>>>(features);
    k_build_all<<<(BATCH*NPALL + 255)/256, 256>>>(fixed_xyz, xyz);
    k_copy_fixed<<<(BATCH*MFIX*3 + 255)/256, 256>>>(fixed_xyz);
    k_fps<<<BATCH, 1024, 3*NPTS*4>>>(xyz);
    k_ball<<<dim3(SQ/48, BATCH), 512, 3*NPALL*4 + 16*NS*4>>>();
    k_gather<<<MROWS/8, 256>>>();

    // layer 1: o1 = h @ W1^T   (K=144 padded, no input transform)
    k_gemm_tf32<0><<<dim3(NMB,1), 256, GEMM_SMEM>>>(gh, KH, w1h, w1l, 128, go1, 128, KH, nullptr, nullptr);
    k_finalize2<<<128, 256>>>(g1, b1, sc0 + 0, bi0 + 0);

    // layer 2: o2 = bn_relu(o1) @ W2^T
    k_gemm_tf32<1><<<dim3(NMB,1), 256, GEMM_SMEM>>>(go1, 128, w2h, w2l, 128, go2, 128, 128, sc0 + 0, bi0 + 0);
    k_finalize2<<<128, 256>>>(g2, b2, sc0 + 256, bi0 + 256);

    // layer 3: o3 = bn_relu(o2) @ W3^T  (N=256)
    k_gemm_tf32<1><<<dim3(NMB,2), 256, GEMM_SMEM>>>(go2, 128, w3h, w3l, 256, go3, 256, 128, sc0 + 256, bi0 + 256);
    k_finalize2<<<256, 256>>>(g3, b3, sc0 + 512, bi0 + 512);

    k_maxpool<<<BATCH*SQ, 256>>>(sc0 + 512, bi0 + 512, out);
    k_writeout<<<(BATCH*SQ*3 + 255)/256, 256>>>(out);
}